// round 17
// baseline (speedup 1.0000x reference)
#include <cuda_runtime.h>
#include <cstdint>

// Verified world (rounds 12/15):
//   in0 tokens i32[16384], in1 batch_input_ids i32[65536],
//   in2 candidate_tokens i32[16384], in3 scores f32[16384], in4 K i32[1]
// Output: 81920 FLOAT32, [updated_tokens (16384) | upd (65536)].
constexpr int B_ = 4;
constexpr int T_ = 4096;
constexpr int S_ = 8192;
constexpr int N_ = B_ * T_;            // 16384
constexpr int UPD_ = 2 * B_ * S_;      // 65536
constexpr int THREADS = 1024;
constexpr int PER = N_ / THREADS;      // 16 keys per thread, contiguous
constexpr int COPY_BLOCKS = 8;

__global__ void __launch_bounds__(THREADS, 1)
fused_kernel(const int*   __restrict__ tok,
             const int*   __restrict__ cand,
             const float* __restrict__ scores,
             const int*   __restrict__ bii,
             const int*   __restrict__ um,
             float*       __restrict__ out) {
    float* out_tokens = out;            // updated_tokens at offset 0
    float* out_upd    = out + N_;       // upd after it
    const int tid = threadIdx.x;

    if (blockIdx.x != 0) {
        // ---- copy CTAs: 32768 non-overwritten upd elements, 4 per thread ---
        const int gt = (blockIdx.x - 1) * THREADS + tid;   // [0, 8192)
        const int j  = gt * 4;                             // [0, 32768) step 4
        int a;
        if (j < N_) {
            a = (j >> 12) * S_ + (j & (T_ - 1));                       // p0 cols [0,4096)
        } else {
            const int jj = j - N_;
            a = (UPD_ / 2) + (jj >> 12) * S_ + T_ + (jj & (T_ - 1));   // p1 cols [4096,8192)
        }
        int4 v = *(const int4*)(bii + a);
        float4 f = make_float4((float)v.x, (float)v.y, (float)v.z, (float)v.w);
        *(float4*)(out_upd + a) = f;
        return;
    }

    // ---------------- block 0: exact top-K radix select ---------------------
    __shared__ unsigned hist[32 * 256];     // per-warp private histograms
    __shared__ unsigned htotq[4 * 256];     // quarter-reduced partials
    __shared__ unsigned long long s_prefix;
    __shared__ unsigned long long s_red;
    __shared__ int s_Krem;
    __shared__ int s_hcount;
    __shared__ int s_done;

    const int lane = tid & 31;
    const int wid  = tid >> 5;
    const int K = *um;                       // 4096 (verified)
    const int i0 = tid * PER;                // contiguous 16 elements/thread

    // ord(score) monotone mapping; keys reconstructed as (ord<<32)|~i.
    unsigned ord[PER];
#pragma unroll
    for (int q = 0; q < PER / 4; ++q) {
        float4 sc = ((const float4*)(scores + i0))[q];
        unsigned u0 = __float_as_uint(sc.x), u1 = __float_as_uint(sc.y);
        unsigned u2 = __float_as_uint(sc.z), u3 = __float_as_uint(sc.w);
        ord[q*4+0] = (u0 & 0x80000000u) ? ~u0 : (u0 | 0x80000000u);
        ord[q*4+1] = (u1 & 0x80000000u) ? ~u1 : (u1 | 0x80000000u);
        ord[q*4+2] = (u2 & 0x80000000u) ? ~u2 : (u2 | 0x80000000u);
        ord[q*4+3] = (u3 & 0x80000000u) ? ~u3 : (u3 | 0x80000000u);
    }

    const bool all_sel  = (K >= N_);
    const bool none_sel = (K <= 0);
    unsigned long long thresh = 0;

    if (!all_sel && !none_sel) {
        if (tid == 0) { s_prefix = 0ull; s_Krem = K; s_done = 0; }

        for (int d = 7; d >= 0; --d) {
            __syncthreads();
            if (s_done) break;                   // uniform
            unsigned long long prefix = s_prefix;
            const int Krem0 = s_Krem;
            const int shift = d * 8;
            const unsigned long long pmask =
                (d == 7) ? 0ull : (~0ull << (shift + 8));

            // zero all private histograms (8192 words / 1024 threads)
#pragma unroll
            for (int z = 0; z < 8; ++z) hist[tid + z * THREADS] = 0;
            __syncthreads();

            // ---- warp-private histogram: NO atomics ----------------------
            unsigned* myhist = hist + wid * 256;
#pragma unroll
            for (int k = 0; k < PER; ++k) {
                const unsigned long long key =
                    ((unsigned long long)ord[k] << 32) |
                    (unsigned)~(i0 + k);
                const bool pred = (key & pmask) == prefix;
                const unsigned act = __ballot_sync(0xFFFFFFFFu, pred);
                if (pred) {
                    const unsigned b = (unsigned)(key >> shift) & 0xFFu;
                    const unsigned m = __match_any_sync(act, b);
                    if (lane == __ffs(m) - 1)        // unique leader per bin
                        myhist[b] += (unsigned)__popc(m);
                }
            }
            __syncthreads();

            // ---- reduce 32 warp-hists -> 4 quarter partials (plain stores)
            {
                const int b = tid & 255, q = tid >> 8;
                unsigned sum = 0;
#pragma unroll
                for (int w = 0; w < 8; ++w) sum += hist[(q * 8 + w) * 256 + b];
                htotq[q * 256 + b] = sum;
            }
            __syncthreads();

            // ---- warp-0: final 4-way sum + parallel suffix scan -----------
            if (tid < 32) {
                unsigned v[8], suf[8];
#pragma unroll
                for (int i = 0; i < 8; ++i) {
                    const int b = lane * 8 + i;
                    v[i] = htotq[b] + htotq[256 + b] + htotq[512 + b] + htotq[768 + b];
                }
                unsigned run = 0;
#pragma unroll
                for (int i = 7; i >= 0; --i) { run += v[i]; suf[i] = run; }
                const unsigned seg = run;
                unsigned acc = seg;
#pragma unroll
                for (int off = 1; off < 32; off <<= 1) {
                    unsigned x = __shfl_down_sync(0xFFFFFFFFu, acc, off);
                    if (lane + off < 32) acc += x;
                }
                const unsigned excl = acc - seg;      // lanes > lane
                const unsigned Kr = (unsigned)Krem0;
#pragma unroll
                for (int i = 0; i < 8; ++i) {
                    const unsigned inc_b = excl + suf[i];
                    const unsigned inc_n = (i < 7) ? (excl + suf[i + 1]) : excl;
                    if (inc_b >= Kr && inc_n < Kr) {  // exactly one crossing
                        s_prefix = prefix |
                            ((unsigned long long)(lane * 8 + i) << shift);
                        s_Krem   = (int)(Kr - inc_n);
                        s_hcount = (int)v[i];
                    }
                }
            }
            __syncthreads();

            prefix = s_prefix;
            const int Krem = s_Krem;
            const int hc   = s_hcount;                // uniform

            if (hc == Krem || Krem == 1 || shift == 0) {
                if (shift == 0) {
                    if (tid == 0) { s_red = prefix; s_done = 1; }
                } else {
                    const unsigned long long gmask = ~0ull << shift;
                    const bool want_min = (hc == Krem);   // K-th = group min
                    if (tid == 0) s_red = want_min ? ~0ull : 0ull;
                    __syncthreads();
#pragma unroll
                    for (int k = 0; k < PER; ++k) {
                        const unsigned long long key =
                            ((unsigned long long)ord[k] << 32) |
                            (unsigned)~(i0 + k);
                        if ((key & gmask) == prefix) {
                            if (want_min) atomicMin(&s_red, key);
                            else          atomicMax(&s_red, key);
                        }
                    }
                    if (tid == 0) s_done = 1;
                }
            }
        }
        __syncthreads();
        thresh = s_red;
    }

    // ---------------- scatter: vectorized float4 writes ---------------------
    const int b  = i0 >> 12;            // same batch row for all 16 elements
    const int t0 = i0 & (T_ - 1);       // 16-aligned column
    float* p0 = out_upd + b * S_ + (S_ - T_) + t0;   // plane 0 tail
    float* p1 = out_upd + B_ * S_ + b * S_ + t0;     // plane 1 head
#pragma unroll
    for (int q = 0; q < PER / 4; ++q) {
        int4 tv = ((const int4*)(tok  + i0))[q];
        int4 cv = ((const int4*)(cand + i0))[q];
        float o[4];
#pragma unroll
        for (int e = 0; e < 4; ++e) {
            const int k = q * 4 + e;
            const unsigned long long key =
                ((unsigned long long)ord[k] << 32) | (unsigned)~(i0 + k);
            const bool sel = all_sel || (!none_sel && key >= thresh);
            const int tve = (e == 0) ? tv.x : (e == 1) ? tv.y : (e == 2) ? tv.z : tv.w;
            const int cve = (e == 0) ? cv.x : (e == 1) ? cv.y : (e == 2) ? cv.z : cv.w;
            o[e] = (float)(sel ? cve : tve);          // exact (< 2^24)
        }
        float4 f = make_float4(o[0], o[1], o[2], o[3]);
        ((float4*)(out_tokens + i0))[q] = f;
        *(float4*)(p0 + q * 4) = f;
        *(float4*)(p1 + q * 4) = f;
    }
}

extern "C" void kernel_launch(void* const* d_in, const int* in_sizes, int n_in,
                              void* d_out, int out_size) {
    const int*   tok    = (const int*)d_in[0];
    const int*   bii    = (const int*)d_in[1];
    const int*   cand   = (const int*)d_in[2];
    const float* scores = (const float*)d_in[3];
    const int*   um     = (const int*)d_in[4];

    fused_kernel<<<1 + COPY_BLOCKS, THREADS>>>(
        tok, cand, scores, bii, um, (float*)d_out);

    (void)in_sizes; (void)n_in; (void)out_size;
}